// round 6
// baseline (speedup 1.0000x reference)
#include <cuda_runtime.h>
#include <cstdint>

// Problem constants
#define BB 256      // batch
#define TT 512      // timesteps
#define DD 128      // input dim
#define HH 512      // hidden
#define KKTOT 640   // D + H fused K per step
#define CC 10       // classes

// Tiling
#define M_BLK 64            // batch rows per CTA
#define NH_BLK 16           // h-columns per CTA
#define NG_BLK 64           // gate columns per CTA
#define NT_N (HH / NH_BLK)  // 32
#define NT_M (BB / M_BLK)   // 4
#define GRID_SZ (NT_M * NT_N)  // 128 CTAs, all co-resident
#define NTHR 512            // 4 k-groups x 128 threads -> 4 warps/SMSP
#define NGRP 4
#define KQ (KKTOT / NGRP)   // 160 K per group
#define KC 16               // k-chunk (10 chunks/group/step)

#define WS_PAD 68                      // padded row stride (floats)
#define WS_FLOATS (KKTOT * WS_PAD)     // 43520 floats = 174,080 B
#define ZBUF_FLOATS (KC * WS_PAD)      // 1088 floats
// 8 Z buffers (2 per group) = 34,816 B; total smem = 209,152 B

// Persistent device state
__device__ float g_h[2][BB * HH];               // h ping-pong
__device__ float g_partial[NT_N][BB][CC];       // partial logits
struct __align__(128) Bar { unsigned count; unsigned gen; unsigned pad[30]; };
__device__ Bar g_mbar[NT_M];                    // per-mtile barriers (32 CTAs each)
__device__ Bar g_fbar;                          // final barrier

// ---------------- per-mtile barrier (32 CTAs) -------------------------------
__device__ __forceinline__ void mtile_barrier(int mt) {
    __threadfence();
    __syncthreads();
    if (threadIdx.x == 0) {
        unsigned old = *((volatile unsigned*)&g_mbar[mt].gen);  // read BEFORE arrive
        unsigned a = atomicAdd(&g_mbar[mt].count, 1u);
        if (a == NT_N - 1u) {
            atomicExch(&g_mbar[mt].count, 0u);
            __threadfence();
            atomicAdd(&g_mbar[mt].gen, 1u);
        } else {
            while (*((volatile unsigned*)&g_mbar[mt].gen) == old) { }
        }
    }
    __syncthreads();
}

// ---------------- packed fp32x2 ops ----------------------------------------
__device__ __forceinline__ void fma2(unsigned long long& acc,
                                     unsigned long long a,
                                     unsigned long long b) {
    asm("fma.rn.f32x2 %0, %1, %2, %0;" : "+l"(acc) : "l"(a), "l"(b));
}
__device__ __forceinline__ unsigned long long add2(unsigned long long a,
                                                   unsigned long long b) {
    unsigned long long r;
    asm("add.rn.f32x2 %0, %1, %2;" : "=l"(r) : "l"(a), "l"(b));
    return r;
}
__device__ __forceinline__ unsigned long long pack2(float v) {
    unsigned long long r;
    unsigned u = __float_as_uint(v);
    asm("mov.b64 %0, {%1, %1};" : "=l"(r) : "r"(u));
    return r;
}

// ---------------- fast activations (MUFU tanh) -----------------------------
__device__ __forceinline__ float fast_tanh(float x) {
    float y;
    asm("tanh.approx.f32 %0, %1;" : "=f"(y) : "f"(x));
    return y;
}
__device__ __forceinline__ float fast_sigmoid(float x) {
    return 0.5f * fast_tanh(0.5f * x) + 0.5f;
}

// ---------------- Z tile staging (per group: 128 thr x 8 floats/chunk) -----
// Z row m = concat(X[b,t,:], h_prev[b,:]) staged transposed Zs[k][m].
// Thread: m = lidx&63, kb = (lidx>>6)*8 -> 8 consecutive k (8-aligned, never
// straddles the X/h boundary at k=128).
__device__ __forceinline__ void load_z8(const float* __restrict__ X,
                                        const float* __restrict__ hprev,
                                        int m0, int t, int kg0, int m,
                                        float4& v0, float4& v1) {
    if (kg0 < DD) {
        const float* s = X + ((size_t)(m0 + m) * TT + t) * DD + kg0;
        v0 = __ldg((const float4*)s);
        v1 = __ldg((const float4*)(s + 4));
    } else {
        const float* s = hprev + (size_t)(m0 + m) * HH + (kg0 - DD);
        v0 = __ldcg((const float4*)s);
        v1 = __ldcg((const float4*)(s + 4));
    }
}
__device__ __forceinline__ void sts_z8(float* zs, int kb, int m,
                                       float4 v0, float4 v1) {
    float* p = zs + kb * WS_PAD + m;    // lanes have consecutive m -> conflict-free
    p[0 * WS_PAD] = v0.x; p[1 * WS_PAD] = v0.y; p[2 * WS_PAD] = v0.z; p[3 * WS_PAD] = v0.w;
    p[4 * WS_PAD] = v1.x; p[5 * WS_PAD] = v1.y; p[6 * WS_PAD] = v1.z; p[7 * WS_PAD] = v1.w;
}

// ---------------- single fused kernel --------------------------------------
__global__ void __launch_bounds__(NTHR, 1)
lstm_all(const float* __restrict__ X,
         const float* __restrict__ W_ih,
         const float* __restrict__ W_hh,
         const float* __restrict__ b_ih,
         const float* __restrict__ b_hh,
         const float* __restrict__ W_lin,
         const float* __restrict__ b_lin,
         float* __restrict__ out)
{
    extern __shared__ float smem[];
    float* Ws  = smem;                            // [KKTOT][WS_PAD]
    float* Zb  = smem + WS_FLOATS;                // 8 x [KC][WS_PAD]
    float* bsm = Zb + 2 * NGRP * ZBUF_FLOATS;     // [NG_BLK]

    const int tid   = threadIdx.x;
    const int cta   = blockIdx.x;
    const int mtile = cta >> 5;
    const int ntile = cta & (NT_N - 1);
    const int m0    = mtile * M_BLK;
    const int c0    = ntile * NH_BLK;

    const int grp   = tid >> 7;                   // 0..3
    const int lidx  = tid & 127;
    const int tx    = lidx & 15;                  // h-column within tile
    const int ty    = lidx >> 4;                  // 0..7; rows ty*8..ty*8+7
    const int kbase = grp * KQ;

    const int sm  = lidx & 63;                    // staging column m
    const int skb = (lidx >> 6) * 8;              // staging k offset in chunk
    float* Zg = Zb + grp * (2 * ZBUF_FLOATS);

    // ---- one-time: W slice into SMEM; column n = 4*j + g, r = g*H + c0 + j
    for (int idx = tid; idx < NG_BLK * KKTOT; idx += NTHR) {
        int k = idx >> 6;
        int n = idx & 63;
        int j = n >> 2, g = n & 3;
        int r = g * HH + c0 + j;
        float v = (k < DD) ? W_ih[r * DD + k] : W_hh[r * HH + (k - DD)];
        Ws[k * WS_PAD + n] = v;
    }
    if (tid < NG_BLK) {
        int j = tid >> 2, g = tid & 3;
        int r = g * HH + c0 + j;
        bsm[tid] = b_ih[r] + b_hh[r];
    }
    // zero this CTA's 2 mtile-local h rows in ping buffer 0
    {
        float* p = &g_h[0][(size_t)(m0 + ntile * 2) * HH];
        for (int i = tid; i < 2 * HH; i += NTHR) p[i] = 0.f;
    }
    __syncthreads();

    float bias_r[4];
#pragma unroll
    for (int g = 0; g < 4; g++) bias_r[g] = bsm[tx * 4 + g];

    mtile_barrier(mtile);   // h0 zeros + W loads (all mtile-local deps)

    unsigned long long acc2[4][4];                // [row-pair][gate]
    float c_st[4], hsum[4];                       // groups 0 & 2 hold state
#pragma unroll
    for (int i = 0; i < 4; i++) { c_st[i] = 0.f; hsum[i] = 0.f; }

    unsigned long long* red = (unsigned long long*)Zb;   // 4352 ull available

    for (int t = 0; t < TT; t++) {
        const float* hprev = g_h[t & 1];
        float* hnext = g_h[(t + 1) & 1];
#pragma unroll
        for (int p = 0; p < 4; p++)
#pragma unroll
            for (int j = 0; j < 4; j++) acc2[p][j] = 0ull;

        float4 v0, v1;
        load_z8(X, hprev, m0, t, kbase + skb, sm, v0, v1);
        sts_z8(Zg, skb, sm, v0, v1);
        __syncthreads();

#pragma unroll 1
        for (int kc = 0; kc < KQ; kc += KC) {
            const float* cur = Zg + ((kc >> 4) & 1) * ZBUF_FLOATS;
            float* nxt       = Zg + (((kc >> 4) + 1) & 1) * ZBUF_FLOATS;
            const bool more = (kc + KC) < KQ;
            if (more) load_z8(X, hprev, m0, t, kbase + kc + KC + skb, sm, v0, v1);

            const float* wrow = Ws + (kbase + kc) * WS_PAD + (tx << 2);
#pragma unroll
            for (int kk = 0; kk < KC; kk++) {
                const float4 wv = *reinterpret_cast<const float4*>(wrow + kk * WS_PAD);
                unsigned long long w0 = pack2(wv.x), w1 = pack2(wv.y),
                                   w2 = pack2(wv.z), w3 = pack2(wv.w);
                const float* zr = cur + kk * WS_PAD + (ty << 3);
                const ulonglong2 za = *reinterpret_cast<const ulonglong2*>(zr);
                const ulonglong2 zc = *reinterpret_cast<const ulonglong2*>(zr + 4);
                fma2(acc2[0][0], za.x, w0); fma2(acc2[0][1], za.x, w1);
                fma2(acc2[0][2], za.x, w2); fma2(acc2[0][3], za.x, w3);
                fma2(acc2[1][0], za.y, w0); fma2(acc2[1][1], za.y, w1);
                fma2(acc2[1][2], za.y, w2); fma2(acc2[1][3], za.y, w3);
                fma2(acc2[2][0], zc.x, w0); fma2(acc2[2][1], zc.x, w1);
                fma2(acc2[2][2], zc.x, w2); fma2(acc2[2][3], zc.x, w3);
                fma2(acc2[3][0], zc.y, w0); fma2(acc2[3][1], zc.y, w1);
                fma2(acc2[3][2], zc.y, w2); fma2(acc2[3][3], zc.y, w3);
            }
            if (more) sts_z8(nxt, skb, sm, v0, v1);
            __syncthreads();
        }

        // ---- 2-stage k-reduction: (g1->g0, g3->g2) then cross-exchange -----
        if (grp == 1) {
#pragma unroll
            for (int p = 0; p < 4; p++)
#pragma unroll
                for (int j = 0; j < 4; j++)
                    red[(p * 4 + j) * 128 + lidx] = acc2[p][j];
        } else if (grp == 3) {
#pragma unroll
            for (int p = 0; p < 4; p++)
#pragma unroll
                for (int j = 0; j < 4; j++)
                    red[2048 + (p * 4 + j) * 128 + lidx] = acc2[p][j];
        }
        __syncthreads();
        if (grp == 0) {
#pragma unroll
            for (int p = 0; p < 4; p++)
#pragma unroll
                for (int j = 0; j < 4; j++)
                    acc2[p][j] = add2(acc2[p][j], red[(p * 4 + j) * 128 + lidx]);
        } else if (grp == 2) {
#pragma unroll
            for (int p = 0; p < 4; p++)
#pragma unroll
                for (int j = 0; j < 4; j++)
                    acc2[p][j] = add2(acc2[p][j], red[2048 + (p * 4 + j) * 128 + lidx]);
        }
        __syncthreads();
        // round 2: g0 sends pairs {2,3}; g2 sends pairs {0,1}
        if (grp == 0) {
#pragma unroll
            for (int p = 2; p < 4; p++)
#pragma unroll
                for (int j = 0; j < 4; j++)
                    red[1024 + ((p - 2) * 4 + j) * 128 + lidx] = acc2[p][j];
        } else if (grp == 2) {
#pragma unroll
            for (int p = 0; p < 2; p++)
#pragma unroll
                for (int j = 0; j < 4; j++)
                    red[(p * 4 + j) * 128 + lidx] = acc2[p][j];
        }
        __syncthreads();

        // ---- epilogue: g0 -> rows 0..3, g2 -> rows 4..7 --------------------
        if ((grp & 1) == 0) {
            const int pbase = grp;         // g0: pairs 0,1 ; g2: pairs 2,3
#pragma unroll
            for (int lp = 0; lp < 2; lp++) {
                const int p = pbase + lp;
                float ga[4][2];
#pragma unroll
                for (int j = 0; j < 4; j++) {
                    unsigned long long other = (grp == 0)
                        ? red[(p * 4 + j) * 128 + lidx]
                        : red[1024 + ((p - 2) * 4 + j) * 128 + lidx];
                    unsigned long long s = add2(acc2[p][j], other);
                    unsigned lo, hi;
                    asm("mov.b64 {%0, %1}, %2;" : "=r"(lo), "=r"(hi) : "l"(s));
                    ga[j][0] = __uint_as_float(lo) + bias_r[j];
                    ga[j][1] = __uint_as_float(hi) + bias_r[j];
                }
#pragma unroll
                for (int hf = 0; hf < 2; hf++) {
                    const int i = lp * 2 + hf;           // local state idx 0..3
                    float ig = fast_sigmoid(ga[0][hf]);
                    float fg = fast_sigmoid(ga[1][hf]);
                    float gg = fast_tanh(ga[2][hf]);
                    float og = fast_sigmoid(ga[3][hf]);
                    float cv = fg * c_st[i] + ig * gg;
                    c_st[i] = cv;
                    float hv = og * fast_tanh(cv);
                    hsum[i] += hv;
                    hnext[(size_t)(m0 + ty * 8 + 2 * p + hf) * HH + c0 + tx] = hv;
                }
            }
        }
        mtile_barrier(mtile);
    }

    // ---- logits partials (groups 0 & 2): shuffle-reduce over tx ------------
    const float inv_t = 1.f / (float)TT;
    if ((grp & 1) == 0) {
        const int rbase = (grp == 0) ? 0 : 4;
#pragma unroll
        for (int i = 0; i < 4; i++) {
            const int b = m0 + ty * 8 + rbase + i;
            const float hm = hsum[i] * inv_t;
#pragma unroll
            for (int cls = 0; cls < CC; cls++) {
                float v = hm * __ldg(&W_lin[cls * HH + c0 + tx]);
                v += __shfl_xor_sync(0xffffffffu, v, 8);
                v += __shfl_xor_sync(0xffffffffu, v, 4);
                v += __shfl_xor_sync(0xffffffffu, v, 2);
                v += __shfl_xor_sync(0xffffffffu, v, 1);
                if (tx == 0) g_partial[ntile][b][cls] = v;
            }
        }
    }

    // ---- final global arrive; CTA 0 reduces to logits ----------------------
    __threadfence();
    __syncthreads();
    if (tid == 0) {
        atomicAdd(&g_fbar.count, 1u);
        if (cta == 0) {
            while (*((volatile unsigned*)&g_fbar.count) < (unsigned)GRID_SZ) { }
            __threadfence();
        }
    }
    __syncthreads();
    if (cta == 0) {
        for (int idx = tid; idx < BB * CC; idx += NTHR) {
            int b = idx / CC, cls = idx % CC;
            float s = __ldg(&b_lin[cls]);
#pragma unroll
            for (int n = 0; n < NT_N; n++) s += __ldcg(&g_partial[n][b][cls]);
            out[idx] = s;
        }
        __syncthreads();
        if (tid == 0) atomicExch(&g_fbar.count, 0u);   // reset for next replay
    }
}

extern "C" void kernel_launch(void* const* d_in, const int* in_sizes, int n_in,
                              void* d_out, int out_size) {
    const float* X     = (const float*)d_in[0];
    const float* W_ih  = (const float*)d_in[1];
    const float* W_hh  = (const float*)d_in[2];
    const float* b_ih  = (const float*)d_in[3];
    const float* b_hh  = (const float*)d_in[4];
    const float* W_lin = (const float*)d_in[5];
    const float* b_lin = (const float*)d_in[6];

    const int smem_bytes =
        (WS_FLOATS + 2 * NGRP * ZBUF_FLOATS + NG_BLK) * (int)sizeof(float);
    cudaFuncSetAttribute(lstm_all,
                         cudaFuncAttributeMaxDynamicSharedMemorySize, smem_bytes);

    lstm_all<<<GRID_SZ, NTHR, smem_bytes>>>(X, W_ih, W_hh, b_ih, b_hh,
                                            W_lin, b_lin, (float*)d_out);
}